// round 12
// baseline (speedup 1.0000x reference)
#include <cuda_runtime.h>
#include <cstdint>

#define BB  8
#define TT  2048
#define DD  1024
#define HSS 64
#define BT  (BB*TT)

// Q/K/V as tf32-rounded fp32, natural layout [BT][HS]. Q pre-scaled by 0.125.
__device__ __align__(16) float g_q[BT*HSS];
__device__ __align__(16) float g_k[BT*HSS];
__device__ __align__(16) float g_v[BT*HSS];
// W stacked+transposed to [n][k] tf32 bits (n = which*64+col, k = 0..1023)
__device__ __align__(16) uint32_t g_wt[192*1024];
// split-K partials: up to 3 splits; unnormalized O and row sums l
__device__ __align__(16) float g_pp[3*BB*2048*HSS];
__device__ float g_ll[3*BB*2048];

__device__ __forceinline__ uint32_t f2tf(float x) {
    uint32_t u;
    asm("cvt.rna.tf32.f32 %0, %1;" : "=r"(u) : "f"(x));
    return u;
}
__device__ __forceinline__ void mma_tf32(float* c, const uint32_t* a,
                                         uint32_t b0, uint32_t b1) {
    asm volatile(
        "mma.sync.aligned.m16n8k8.row.col.f32.tf32.tf32.f32 "
        "{%0,%1,%2,%3}, {%4,%5,%6,%7}, {%8,%9}, {%0,%1,%2,%3};"
        : "+f"(c[0]), "+f"(c[1]), "+f"(c[2]), "+f"(c[3])
        : "r"(a[0]), "r"(a[1]), "r"(a[2]), "r"(a[3]), "r"(b0), "r"(b1));
}
__device__ __forceinline__ uint32_t smem_u32(const void* p) {
    uint32_t a;
    asm("{ .reg .u64 t; cvta.to.shared.u64 t, %1; cvt.u32.u64 %0, t; }"
        : "=r"(a) : "l"(p));
    return a;
}
__device__ __forceinline__ void cp16(uint32_t dst, const void* src) {
    asm volatile("cp.async.ca.shared.global [%0], [%1], 16;"
                 :: "r"(dst), "l"(src));
}
#define CP_COMMIT() asm volatile("cp.async.commit_group;")

// ---------------------------------------------------------------------------
// Kernel 0: convert W (stacked, transposed) fp32 -> tf32 bits  [192 n][1024 k]
// ---------------------------------------------------------------------------
__global__ void wconv_kernel(const float* __restrict__ Wq,
                             const float* __restrict__ Wk,
                             const float* __restrict__ Wv)
{
    const int n   = blockIdx.x;
    const int col = n & 63;
    const float* W = (n < 64) ? Wq : (n < 128) ? Wk : Wv;
    for (int i = 0; i < 4; i++) {
        int k = threadIdx.x + i * 256;
        g_wt[n * 1024 + k] = f2tf(W[(size_t)k * HSS + col]);
    }
}

// ---------------------------------------------------------------------------
// Kernel 1: FUSED QKV projection on mma.m16n8k8.tf32 (unchanged from R11).
// grid = 256 Mtiles (M=64), block = 256 (8 warps: 2 wm x 4 wn; warp 32 x 48).
// ---------------------------------------------------------------------------
#define LDX 36

__global__ __launch_bounds__(256, 2) void projmma_kernel(const float* __restrict__ X)
{
    extern __shared__ uint32_t smu[];
    uint32_t* Xs = smu;             // [64][36]
    uint32_t* Ws = smu + 64*LDX;    // [192][36]

    const int row0  = blockIdx.x * 64;
    const int tid   = threadIdx.x;
    const int wid   = tid >> 5;
    const int lane  = tid & 31;
    const int grp   = lane >> 2;
    const int tig   = lane & 3;
    const int wm    = wid >> 2;
    const int wn    = wid & 3;

    float acc[2][6][4];
    #pragma unroll
    for (int i = 0; i < 2; i++)
        #pragma unroll
        for (int nb = 0; nb < 6; nb++)
            #pragma unroll
            for (int r = 0; r < 4; r++) acc[i][nb][r] = 0.f;

    float4 xa[2];
    uint4  wb[6];
    {
        #pragma unroll
        for (int t = 0; t < 2; t++) {
            int f = tid + t * 256;
            int r = f >> 3, c = (f & 7) * 4;
            xa[t] = *(const float4*)&X[(size_t)(row0 + r) * DD + c];
        }
        #pragma unroll
        for (int t = 0; t < 6; t++) {
            int f = tid + t * 256;
            int n = f >> 3, kc = (f & 7) * 4;
            wb[t] = *(const uint4*)&g_wt[(size_t)n * 1024 + kc];
        }
    }

    for (int k0 = 0; k0 < DD; k0 += 32) {
        #pragma unroll
        for (int t = 0; t < 2; t++) {
            int f = tid + t * 256;
            int r = f >> 3, c = (f & 7) * 4;
            float4 v = xa[t];
            uint4 u = make_uint4(f2tf(v.x), f2tf(v.y), f2tf(v.z), f2tf(v.w));
            *(uint4*)&Xs[r*LDX + c] = u;
        }
        #pragma unroll
        for (int t = 0; t < 6; t++) {
            int f = tid + t * 256;
            int n = f >> 3, kc = (f & 7) * 4;
            *(uint4*)&Ws[n*LDX + kc] = wb[t];
        }
        __syncthreads();

        if (k0 + 32 < DD) {
            int kn = k0 + 32;
            #pragma unroll
            for (int t = 0; t < 2; t++) {
                int f = tid + t * 256;
                int r = f >> 3, c = (f & 7) * 4;
                xa[t] = *(const float4*)&X[(size_t)(row0 + r) * DD + kn + c];
            }
            #pragma unroll
            for (int t = 0; t < 6; t++) {
                int f = tid + t * 256;
                int n = f >> 3, kc = (f & 7) * 4;
                wb[t] = *(const uint4*)&g_wt[(size_t)n * 1024 + kn + kc];
            }
        }

        #pragma unroll
        for (int ks = 0; ks < 4; ks++) {
            const int kk = ks * 8;
            uint32_t af[2][4];
            #pragma unroll
            for (int i = 0; i < 2; i++) {
                int mb = wm*32 + i*16;
                af[i][0] = Xs[(mb + grp    )*LDX + kk + tig];
                af[i][1] = Xs[(mb + grp + 8)*LDX + kk + tig];
                af[i][2] = Xs[(mb + grp    )*LDX + kk + tig + 4];
                af[i][3] = Xs[(mb + grp + 8)*LDX + kk + tig + 4];
            }
            #pragma unroll
            for (int nb = 0; nb < 6; nb++) {
                int n0 = wn*48 + nb*8;
                uint32_t b0 = Ws[(n0 + grp)*LDX + kk + tig];
                uint32_t b1 = Ws[(n0 + grp)*LDX + kk + tig + 4];
                mma_tf32(acc[0][nb], af[0], b0, b1);
                mma_tf32(acc[1][nb], af[1], b0, b1);
            }
        }
        __syncthreads();
    }

    #pragma unroll
    for (int nb = 0; nb < 6; nb++) {
        const int gc0   = wn*48 + nb*8;
        const int which = gc0 >> 6;
        const int c     = (gc0 & 63) + 2*tig;
        const float sc  = (which == 0) ? 0.125f : 1.0f;
        float* O = (which == 0) ? g_q : (which == 1) ? g_k : g_v;
        #pragma unroll
        for (int i = 0; i < 2; i++) {
            int r = row0 + wm*32 + i*16 + grp;
            float2 v0 = make_float2(
                __uint_as_float(f2tf(acc[i][nb][0] * sc)),
                __uint_as_float(f2tf(acc[i][nb][1] * sc)));
            float2 v1 = make_float2(
                __uint_as_float(f2tf(acc[i][nb][2] * sc)),
                __uint_as_float(f2tf(acc[i][nb][3] * sc)));
            *(float2*)&O[(size_t)r * HSS + c]       = v0;
            *(float2*)&O[(size_t)(r + 8) * HSS + c] = v1;
        }
    }
}

// ---------------------------------------------------------------------------
// Kernel 2: FA2-style causal attention, generalized split-K (<=11 chunks/CTA).
// grid = (63, 8), block = 128. s=3 for qti>=22, s=2 for 11..21, s=1 else.
// Q staged THROUGH K buffer (no Qs) => smem 71.7KB => 3 CTAs/SM.
// Diagonal chunks skip fully-masked key blocks per warp.
// ---------------------------------------------------------------------------
#define LDQ 68
#define LDV 72

__global__ __launch_bounds__(128, 3) void attn_kernel(float* __restrict__ Out)
{
    extern __shared__ uint32_t smu[];
    uint32_t* Ks = smu;              // [2][64][68]
    uint32_t* Vs = smu + 2*64*LDQ;   // [2][64][72]

    const int b   = blockIdx.y;
    const int idx = blockIdx.x;
    int qti, z, s;
    if (idx < 30)      { qti = 31 - idx/3;              z = idx % 3;  s = 3; }
    else if (idx < 52) { int j = idx - 30; qti = 21 - (j >> 1); z = j & 1; s = 2; }
    else               { qti = 10 - (idx - 52);         z = 0;        s = 1; }
    const int nch  = qti + 1;
    const int base = nch / s, rem = nch % s;
    const int c0   = z * base + (z < rem ? z : rem);
    const int c1   = c0 + base + (z < rem ? 1 : 0);
    const int q0   = qti * 64;
    const bool split = (s > 1);

    const int tid  = threadIdx.x;
    const int wid  = tid >> 5;
    const int lane = tid & 31;
    const int m0   = wid * 16;
    const int grp  = lane >> 2;
    const int tig  = lane & 3;
    const int src  = (lane & ~3) | (tig >> 1);
    const int src2 = src + 2;

    const uint32_t ks_b = smem_u32(Ks);
    const uint32_t vs_b = smem_u32(Vs);

    // ---- stage Q through K buffer 0 via cp.async, extract persistent frags
    {
        const size_t qbase = (size_t)(b * TT + q0) * HSS;
        #pragma unroll
        for (int t = 0; t < 8; t++) {
            int f = tid + t * 128;
            int r = f >> 4, c = (f & 15) * 4;
            cp16(ks_b + (r*LDQ + c)*4, &g_q[qbase + (size_t)r*HSS + c]);
        }
        CP_COMMIT();
        asm volatile("cp.async.wait_group 0;");
        __syncthreads();
    }
    uint32_t qf[8][4];
    #pragma unroll
    for (int ks = 0; ks < 8; ks++) {
        int base2 = (m0 + grp)*LDQ + ks*8 + tig;
        qf[ks][0] = Ks[base2];
        qf[ks][1] = Ks[base2 + 8*LDQ];
        qf[ks][2] = Ks[base2 + 4];
        qf[ks][3] = Ks[base2 + 8*LDQ + 4];
    }
    __syncthreads();   // everyone extracted; K buffer 0 reusable

    // ---- prefetch first K/V chunk into buffer 0
    {
        const size_t kvb = (size_t)(b * TT + c0 * 64) * HSS;
        #pragma unroll
        for (int t = 0; t < 8; t++) {
            int f = tid + t * 128;
            int r = f >> 4, c = (f & 15) * 4;
            cp16(ks_b + (r*LDQ + c)*4, &g_k[kvb + (size_t)r*HSS + c]);
            cp16(vs_b + (r*LDV + c)*4, &g_v[kvb + (size_t)r*HSS + c]);
        }
        CP_COMMIT();
    }

    float accO[8][4];
    #pragma unroll
    for (int n = 0; n < 8; n++)
        #pragma unroll
        for (int i = 0; i < 4; i++) accO[n][i] = 0.f;
    float rs0 = 0.f, rs1 = 0.f;

    for (int ch = c0; ch < c1; ch++) {
        const int buf = (ch - c0) & 1;
        const uint32_t kb = ks_b + (uint32_t)(buf * 64*LDQ*4);
        const uint32_t vb = vs_b + (uint32_t)(buf * 64*LDV*4);

        if (ch + 1 < c1) {
            const int nb2 = buf ^ 1;
            const uint32_t kb2 = ks_b + (uint32_t)(nb2 * 64*LDQ*4);
            const uint32_t vb2 = vs_b + (uint32_t)(nb2 * 64*LDV*4);
            const size_t kvb = (size_t)(b * TT + (ch+1)*64) * HSS;
            #pragma unroll
            for (int t = 0; t < 8; t++) {
                int f = tid + t * 128;
                int r = f >> 4, c = (f & 15) * 4;
                cp16(kb2 + (r*LDQ + c)*4, &g_k[kvb + (size_t)r*HSS + c]);
                cp16(vb2 + (r*LDV + c)*4, &g_v[kvb + (size_t)r*HSS + c]);
            }
            CP_COMMIT();
            asm volatile("cp.async.wait_group 1;");
        } else {
            asm volatile("cp.async.wait_group 0;");
        }
        __syncthreads();

        const uint32_t* Kb = smu + (kb - smem_u32(smu)) / 4;
        const uint32_t* Vb = smu + (vb - smem_u32(smu)) / 4;

        const bool diag  = (ch == qti);
        const int  nbmax = diag ? (2*wid + 2) : 8;   // warp-uniform

        // ---- S = Q K^T
        float accS[8][4];
        #pragma unroll
        for (int n = 0; n < 8; n++)
            #pragma unroll
            for (int i = 0; i < 4; i++) accS[n][i] = 0.f;

        #pragma unroll
        for (int ks = 0; ks < 8; ks++) {
            #pragma unroll
            for (int nb = 0; nb < 8; nb++) {
                if (nb < nbmax) {
                    int base2 = (8*nb + grp)*LDQ + 8*ks + tig;
                    uint32_t b0 = Kb[base2];
                    uint32_t b1 = Kb[base2 + 4];
                    mma_tf32(accS[nb], qf[ks], b0, b1);
                }
            }
        }

        // ---- mask + exp(s-8) + row sums + cvt to tf32 bits
        const int l0 = diag ? (m0 + grp)     : (1 << 30);
        const int l1 = diag ? (m0 + grp + 8) : (1 << 30);
        uint32_t p[8][4];
        #pragma unroll
        for (int nb = 0; nb < 8; nb++) {
            if (nb < nbmax) {
                int cl = 8*nb + 2*tig;
                float p0 = (cl     > l0) ? 0.f : __expf(accS[nb][0] - 8.f);
                float p1 = (cl + 1 > l0) ? 0.f : __expf(accS[nb][1] - 8.f);
                float p2 = (cl     > l1) ? 0.f : __expf(accS[nb][2] - 8.f);
                float p3 = (cl + 1 > l1) ? 0.f : __expf(accS[nb][3] - 8.f);
                rs0 += p0 + p1;
                rs1 += p2 + p3;
                p[nb][0] = f2tf(p0); p[nb][1] = f2tf(p1);
                p[nb][2] = f2tf(p2); p[nb][3] = f2tf(p3);
            }
        }

        // ---- O += P V (skip all-zero-P key blocks on diagonal)
        #pragma unroll
        for (int kf = 0; kf < 8; kf++) {
            if (kf < nbmax) {
                uint32_t v00 = __shfl_sync(0xffffffffu, p[kf][0], src);
                uint32_t v01 = __shfl_sync(0xffffffffu, p[kf][1], src);
                uint32_t v02 = __shfl_sync(0xffffffffu, p[kf][2], src);
                uint32_t v03 = __shfl_sync(0xffffffffu, p[kf][3], src);
                uint32_t v10 = __shfl_sync(0xffffffffu, p[kf][0], src2);
                uint32_t v11 = __shfl_sync(0xffffffffu, p[kf][1], src2);
                uint32_t v12 = __shfl_sync(0xffffffffu, p[kf][2], src2);
                uint32_t v13 = __shfl_sync(0xffffffffu, p[kf][3], src2);
                const bool odd = tig & 1;
                uint32_t a[4];
                a[0] = odd ? v01 : v00;
                a[1] = odd ? v03 : v02;
                a[2] = odd ? v11 : v10;
                a[3] = odd ? v13 : v12;
                #pragma unroll
                for (int nb = 0; nb < 8; nb++) {
                    uint32_t b0 = Vb[(8*kf + tig    )*LDV + 8*nb + grp];
                    uint32_t b1 = Vb[(8*kf + tig + 4)*LDV + 8*nb + grp];
                    mma_tf32(accO[nb], a, b0, b1);
                }
            }
        }
        __syncthreads();
    }

    // row-sum quad reduction
    rs0 += __shfl_xor_sync(0xffffffffu, rs0, 1);
    rs0 += __shfl_xor_sync(0xffffffffu, rs0, 2);
    rs1 += __shfl_xor_sync(0xffffffffu, rs1, 1);
    rs1 += __shfl_xor_sync(0xffffffffu, rs1, 2);

    if (split) {
        float* P = g_pp + ((size_t)(z * BB + b) * 2048 + q0 + m0) * HSS;
        float* L = g_ll + (size_t)(z * BB + b) * 2048 + q0 + m0;
        #pragma unroll
        for (int nb = 0; nb < 8; nb++) {
            int c = 8*nb + 2*tig;
            *(float2*)&P[(size_t)grp*HSS + c] =
                make_float2(accO[nb][0], accO[nb][1]);
            *(float2*)&P[(size_t)(grp + 8)*HSS + c] =
                make_float2(accO[nb][2], accO[nb][3]);
        }
        if (tig == 0) {
            L[grp]     = rs0;
            L[grp + 8] = rs1;
        }
    } else {
        const float inv0 = 1.f / rs0;
        const float inv1 = 1.f / rs1;
        const size_t ob = (size_t)(b * TT + q0 + m0) * HSS;
        #pragma unroll
        for (int nb = 0; nb < 8; nb++) {
            int c = 8*nb + 2*tig;
            float2 v0 = make_float2(accO[nb][0]*inv0, accO[nb][1]*inv0);
            float2 v1 = make_float2(accO[nb][2]*inv1, accO[nb][3]*inv1);
            *(float2*)&Out[ob + (size_t)grp*HSS + c]       = v0;
            *(float2*)&Out[ob + (size_t)(grp + 8)*HSS + c] = v1;
        }
    }
}

// ---------------------------------------------------------------------------
// Kernel 3: combine split-K partials for q in [704, 2048)  (qti >= 11).
// grid = 672, block = 256; one float4 of output per thread.
// ---------------------------------------------------------------------------
__global__ void combine_kernel(float* __restrict__ Out)
{
    int f  = blockIdx.x * 256 + threadIdx.x;   // 0 .. 8*1344*16
    int d4 = (f & 15) * 4;
    int qi = (f >> 4) % 1344;
    int b  = (f >> 4) / 1344;
    int q  = 704 + qi;
    int qti = q >> 6;
    int ns = (qti >= 22) ? 3 : 2;

    float l = 0.f;
    float4 o = make_float4(0.f, 0.f, 0.f, 0.f);
    for (int zz = 0; zz < ns; zz++) {
        l += g_ll[(size_t)(zz * BB + b) * 2048 + q];
        const float4 a = *(const float4*)
            &g_pp[((size_t)(zz * BB + b) * 2048 + q) * HSS + d4];
        o.x += a.x; o.y += a.y; o.z += a.z; o.w += a.w;
    }
    float inv = 1.f / l;
    o.x *= inv; o.y *= inv; o.z *= inv; o.w *= inv;
    *(float4*)&Out[((size_t)(b * TT + q)) * HSS + d4] = o;
}

// ---------------------------------------------------------------------------
extern "C" void kernel_launch(void* const* d_in, const int* in_sizes, int n_in,
                              void* d_out, int out_size)
{
    const float* X  = (const float*)d_in[0];
    const float* Wq = (const float*)d_in[1];
    const float* Wk = (const float*)d_in[2];
    const float* Wv = (const float*)d_in[3];
    float* Out = (float*)d_out;

    wconv_kernel<<<192, 256>>>(Wq, Wk, Wv);

    const int proj_smem = (64*LDX + 192*LDX) * 4;              // 36864 B
    projmma_kernel<<<256, 256, proj_smem>>>(X);

    const int attn_smem = (2*64*LDQ + 2*64*LDV) * 4;           // 71680 B
    cudaFuncSetAttribute(attn_kernel,
        cudaFuncAttributeMaxDynamicSharedMemorySize, attn_smem);
    dim3 g2(63, BB);
    attn_kernel<<<g2, 128, attn_smem>>>(Out);

    combine_kernel<<<672, 256>>>(Out);
}